// round 1
// baseline (speedup 1.0000x reference)
#include <cuda_runtime.h>

// Problem constants (fixed shapes for this benchmark)
#define NW 16384   // words
#define WL 16      // word length (chars)
#define D  300     // hidden dim
#define NL 128     // letters
#define KS 3       // kernel size
#define CH 75      // float4 chunks per 300-float row

// Scratch (device globals — no allocation allowed in kernel_launch)
__device__ float g_wT[KS][D][D];   // w transposed: [k][i][o]
__device__ float g_P[KS][NL][D];   // per-letter conv partials: [k][letter][o]

// ---------------------------------------------------------------------------
// Kernel 0: transpose conv_w [O,I,K] -> wT [K][I][O] so the P kernel can read
// coalesced along O.
// ---------------------------------------------------------------------------
__global__ void transpose_w_kernel(const float* __restrict__ w) {
    int idx = blockIdx.x * blockDim.x + threadIdx.x;
    if (idx >= KS * D * D) return;
    int o = idx % D;
    int i = (idx / D) % D;
    int k = idx / (D * D);
    g_wT[k][i][o] = w[(o * D + i) * KS + k];
}

// ---------------------------------------------------------------------------
// Kernel 1: P[k][v][o] = sum_i emb[v,i] * w[o,i,k]
// One block per (k, letter v). Thread t computes a float4 of o-channels.
// emb[v,i] is a warp-uniform broadcast load; wT row read is coalesced.
// ---------------------------------------------------------------------------
__global__ __launch_bounds__(96) void compute_P_kernel(const float* __restrict__ emb) {
    int k = blockIdx.x >> 7;      // grid = KS*NL = 384
    int v = blockIdx.x & 127;
    int t = threadIdx.x;          // 0..95, only 0..74 active
    if (t >= CH) return;

    const float* er = emb + v * D;
    float4 acc = make_float4(0.f, 0.f, 0.f, 0.f);
#pragma unroll 4
    for (int i = 0; i < D; ++i) {
        float e = __ldg(er + i);
        float4 wv = ((const float4*)g_wT[k][i])[t];
        acc.x = fmaf(e, wv.x, acc.x);
        acc.y = fmaf(e, wv.y, acc.y);
        acc.z = fmaf(e, wv.z, acc.z);
        acc.w = fmaf(e, wv.w, acc.w);
    }
    ((float4*)g_P[k][v])[t] = acc;
}

// ---------------------------------------------------------------------------
// Kernel 2: main pass. One warp per word. Each lane owns float4 channel
// chunks {lane, lane+32, lane+64}. For each position l, sum the three
// letter-partial rows, track running max; bias + ReLU at the end.
// ---------------------------------------------------------------------------
__device__ __forceinline__ void add4(float4& a, float4 b) {
    a.x += b.x; a.y += b.y; a.z += b.z; a.w += b.w;
}
__device__ __forceinline__ void max4(float4& a, float4 b) {
    a.x = fmaxf(a.x, b.x); a.y = fmaxf(a.y, b.y);
    a.z = fmaxf(a.z, b.z); a.w = fmaxf(a.w, b.w);
}

__global__ __launch_bounds__(256) void encode_kernel(const int* __restrict__ words,
                                                     const float* __restrict__ bias,
                                                     float* __restrict__ out) {
    int gw   = (blockIdx.x * blockDim.x + threadIdx.x) >> 5;  // word index
    int lane = threadIdx.x & 31;
    if (gw >= NW) return;

    // Letters for this word: words is [WL, NW], lane l reads char l.
    int cval = 0;
    if (lane < WL) cval = words[lane * NW + gw];
    int let[WL];
#pragma unroll
    for (int l = 0; l < WL; ++l) let[l] = __shfl_sync(0xffffffffu, cval, l);

    const int ch0 = lane, ch1 = lane + 32, ch2 = lane + 64;
    const bool has2 = (ch2 < CH);

    const float NEG = -1e30f;
    float4 a0 = make_float4(NEG, NEG, NEG, NEG);
    float4 a1 = a0, a2 = a0;

#pragma unroll
    for (int l = 0; l < WL; ++l) {
        const float4* p1 = (const float4*)g_P[1][let[l]];
        float4 s0 = p1[ch0];
        float4 s1 = p1[ch1];
        float4 s2 = has2 ? p1[ch2] : make_float4(0.f, 0.f, 0.f, 0.f);

        if (l > 0) {
            const float4* p0 = (const float4*)g_P[0][let[l - 1]];
            add4(s0, p0[ch0]); add4(s1, p0[ch1]);
            if (has2) add4(s2, p0[ch2]);
        }
        if (l < WL - 1) {
            const float4* p2 = (const float4*)g_P[2][let[l + 1]];
            add4(s0, p2[ch0]); add4(s1, p2[ch1]);
            if (has2) add4(s2, p2[ch2]);
        }
        max4(a0, s0); max4(a1, s1);
        if (has2) max4(a2, s2);
    }

    const float4* b4 = (const float4*)bias;
    float4* o4 = (float4*)out + (size_t)gw * CH;

    float4 bb = b4[ch0];
    float4 r;
    r.x = fmaxf(a0.x + bb.x, 0.f); r.y = fmaxf(a0.y + bb.y, 0.f);
    r.z = fmaxf(a0.z + bb.z, 0.f); r.w = fmaxf(a0.w + bb.w, 0.f);
    o4[ch0] = r;

    bb = b4[ch1];
    r.x = fmaxf(a1.x + bb.x, 0.f); r.y = fmaxf(a1.y + bb.y, 0.f);
    r.z = fmaxf(a1.z + bb.z, 0.f); r.w = fmaxf(a1.w + bb.w, 0.f);
    o4[ch1] = r;

    if (has2) {
        bb = b4[ch2];
        r.x = fmaxf(a2.x + bb.x, 0.f); r.y = fmaxf(a2.y + bb.y, 0.f);
        r.z = fmaxf(a2.z + bb.z, 0.f); r.w = fmaxf(a2.w + bb.w, 0.f);
        o4[ch2] = r;
    }
}

// ---------------------------------------------------------------------------
// Launch: inputs per metadata order: words_batch(int32), emb_table(f32),
// conv_w(f32), conv_b(f32). Output f32 [NW, D].
// ---------------------------------------------------------------------------
extern "C" void kernel_launch(void* const* d_in, const int* in_sizes, int n_in,
                              void* d_out, int out_size) {
    const int*   words = (const int*)d_in[0];
    const float* emb   = (const float*)d_in[1];
    const float* w     = (const float*)d_in[2];
    const float* b     = (const float*)d_in[3];
    float*       out   = (float*)d_out;

    transpose_w_kernel<<<(KS * D * D + 255) / 256, 256>>>(w);
    compute_P_kernel<<<KS * NL, 96>>>(emb);
    encode_kernel<<<NW / 8, 256>>>(words, b, out);  // 8 warps/block, 1 warp/word
}

// round 2
// speedup vs baseline: 1.3827x; 1.3827x over previous
#include <cuda_runtime.h>

// Problem constants
#define NW 16384   // words
#define WL 16      // word length
#define D  300     // hidden dim
#define NL 128     // letters
#define KS 3       // conv kernel size

// Channel slicing for the smem-resident encode pass
#define SW   100   // channels per slice
#define SW4  25    // float4 chunks per slice
#define NSL  3     // slices (3*100 = 300)

#define G_X  49    // word-blocks per slice (49*3 = 147 blocks ~= 1 wave @ 1 CTA/SM)
#define WPB  16    // warps per block (512 threads)

#define ENC_SMEM (KS * NL * SW * 4)   // 153600 B

// Per-letter conv partials: P[k][v][o] = sum_i emb[v,i] * w[o,i,k]
__device__ float g_P[KS][NL][D];

// ---------------------------------------------------------------------------
// Kernel 1: build P. One block per output channel o (300 blocks, 128 threads).
// Loads the contiguous 900-float w[o] row to smem (coalesced), each thread
// owns one letter v and accumulates the 3 taps.
// ---------------------------------------------------------------------------
__global__ __launch_bounds__(128) void compute_P_kernel(const float* __restrict__ emb,
                                                        const float* __restrict__ w) {
    __shared__ float ws[D * KS];  // w[o][i][k], 3.6 KB
    int o = blockIdx.x;
    for (int i = threadIdx.x; i < D * KS; i += 128) ws[i] = w[o * D * KS + i];
    __syncthreads();

    int v = threadIdx.x;  // 0..127
    const float* er = emb + v * D;
    float a0 = 0.f, a1 = 0.f, a2 = 0.f;
#pragma unroll 4
    for (int i = 0; i < D; ++i) {
        float e = __ldg(er + i);
        a0 = fmaf(e, ws[i * 3 + 0], a0);
        a1 = fmaf(e, ws[i * 3 + 1], a1);
        a2 = fmaf(e, ws[i * 3 + 2], a2);
    }
    g_P[0][v][o] = a0;
    g_P[1][v][o] = a1;
    g_P[2][v][o] = a2;
}

// ---------------------------------------------------------------------------
// Kernel 2: encode. grid = (G_X word-blocks, NSL slices). Each block stages
// its 153.6 KB P-slice in smem, then each warp walks words: 3 conflict-free
// LDS.128 gathers per position, running per-channel max, bias+ReLU at end.
// ---------------------------------------------------------------------------
__device__ __forceinline__ void add4(float4& a, float4 b) {
    a.x += b.x; a.y += b.y; a.z += b.z; a.w += b.w;
}
__device__ __forceinline__ void max4(float4& a, float4 b) {
    a.x = fmaxf(a.x, b.x); a.y = fmaxf(a.y, b.y);
    a.z = fmaxf(a.z, b.z); a.w = fmaxf(a.w, b.w);
}

__global__ __launch_bounds__(32 * WPB) void encode_kernel(const int* __restrict__ words,
                                                          const float* __restrict__ bias,
                                                          float* __restrict__ out) {
    extern __shared__ float4 Ps[];  // [KS*NL][SW4] float4 rows
    const int s  = blockIdx.y;
    const int c0 = s * SW;

    // Stage this slice of the P table: rows r = k*128+v, SW4 float4 each.
    for (int idx = threadIdx.x; idx < KS * NL * SW4; idx += blockDim.x) {
        int r = idx / SW4;
        int c = idx % SW4;
        int k = r >> 7, v = r & 127;
        Ps[idx] = *(const float4*)&g_P[k][v][c0 + c * 4];
    }
    __syncthreads();

    const int lane  = threadIdx.x & 31;
    const int warp0 = blockIdx.x * WPB + (threadIdx.x >> 5);
    const int nwarp = G_X * WPB;

    float4 bb = make_float4(0.f, 0.f, 0.f, 0.f);
    if (lane < SW4) bb = *(const float4*)&bias[c0 + lane * 4];

    for (int gw = warp0; gw < NW; gw += nwarp) {
        // Fetch the word's letters: words is [WL, NW].
        int cval = 0;
        if (lane < WL) cval = words[lane * NW + gw];
        int let[WL];
#pragma unroll
        for (int l = 0; l < WL; ++l) let[l] = __shfl_sync(0xffffffffu, cval, l);

        if (lane < SW4) {
            const float NEG = -1e30f;
            float4 a = make_float4(NEG, NEG, NEG, NEG);
#pragma unroll
            for (int l = 0; l < WL; ++l) {
                float4 sd = Ps[(NL + let[l]) * SW4 + lane];             // k=1, this char
                if (l > 0)      add4(sd, Ps[let[l - 1] * SW4 + lane]);  // k=0, prev char
                if (l < WL - 1) add4(sd, Ps[(2 * NL + let[l + 1]) * SW4 + lane]);  // k=2
                max4(a, sd);
            }
            float4 r;
            r.x = fmaxf(a.x + bb.x, 0.f);
            r.y = fmaxf(a.y + bb.y, 0.f);
            r.z = fmaxf(a.z + bb.z, 0.f);
            r.w = fmaxf(a.w + bb.w, 0.f);
            *(float4*)&out[(size_t)gw * D + c0 + lane * 4] = r;
        }
    }
}

// ---------------------------------------------------------------------------
// Launch. Inputs: words(int32), emb(f32), conv_w(f32), conv_b(f32). Out f32.
// ---------------------------------------------------------------------------
extern "C" void kernel_launch(void* const* d_in, const int* in_sizes, int n_in,
                              void* d_out, int out_size) {
    const int*   words = (const int*)d_in[0];
    const float* emb   = (const float*)d_in[1];
    const float* w     = (const float*)d_in[2];
    const float* b     = (const float*)d_in[3];
    float*       out   = (float*)d_out;

    compute_P_kernel<<<D, 128>>>(emb, w);

    cudaFuncSetAttribute(encode_kernel,
                         cudaFuncAttributeMaxDynamicSharedMemorySize, ENC_SMEM);
    encode_kernel<<<dim3(G_X, NSL), 32 * WPB, ENC_SMEM>>>(words, b, out);
}

// round 3
// speedup vs baseline: 1.7621x; 1.2744x over previous
#include <cuda_runtime.h>

// Problem constants
#define NW 16384   // words
#define WL 16      // word length
#define D  300     // hidden dim
#define NL 128     // letters
#define KS 3       // conv kernel size

// Encode slicing: 5 slices of 60 channels -> 92 KB smem/CTA -> 2 CTA/SM
#define SW   60
#define SW4  15    // float4 chunks per slice
#define NSL  5
#define G_X  59    // word-blocks per slice (59*5 = 295 ~= 2 waves worth of CTAs)
#define WPB  16    // warps per block (512 threads)
#define ENC_SMEM (KS * NL * SW * 4)   // 92160 B

// Per-letter conv partials: P[k][v][o] = sum_i emb[v,i] * w[o,i,k]
__device__ float g_P[KS][NL][D];

// ---------------------------------------------------------------------------
// Kernel 1: build P. Block per output channel o (300 blocks, 128 threads).
// w[o] row staged in smem (coalesced). Each thread owns letter v and reads
// its emb row via float4 __ldg (8 chunks/line -> high L1 hit rate), full
// unroll for memory-level parallelism.
// ---------------------------------------------------------------------------
__global__ __launch_bounds__(128) void compute_P_kernel(const float* __restrict__ emb,
                                                        const float* __restrict__ w) {
    __shared__ float ws[D * KS];  // w[o][i][k], 3.6 KB
    int o = blockIdx.x;
    for (int i = threadIdx.x; i < D * KS; i += 128) ws[i] = w[o * D * KS + i];
    __syncthreads();

    int v = threadIdx.x;  // letter
    const float4* er = (const float4*)(emb + v * D);  // 75 float4 chunks
    float a0 = 0.f, a1 = 0.f, a2 = 0.f;
#pragma unroll
    for (int c = 0; c < D / 4; ++c) {
        float4 e = __ldg(er + c);
        const float* wr = &ws[c * 12];  // 4 input channels * 3 taps
        a0 = fmaf(e.x, wr[0],  a0); a1 = fmaf(e.x, wr[1],  a1); a2 = fmaf(e.x, wr[2],  a2);
        a0 = fmaf(e.y, wr[3],  a0); a1 = fmaf(e.y, wr[4],  a1); a2 = fmaf(e.y, wr[5],  a2);
        a0 = fmaf(e.z, wr[6],  a0); a1 = fmaf(e.z, wr[7],  a1); a2 = fmaf(e.z, wr[8],  a2);
        a0 = fmaf(e.w, wr[9],  a0); a1 = fmaf(e.w, wr[10], a1); a2 = fmaf(e.w, wr[11], a2);
    }
    g_P[0][v][o] = a0;
    g_P[1][v][o] = a1;
    g_P[2][v][o] = a2;
}

// ---------------------------------------------------------------------------
// Kernel 2: encode. grid = (G_X, NSL). Block stages its 92 KB P-slice in
// smem; each warp processes TWO words per iteration (lanes 0-14 word A,
// 16-30 word B). 3 conflict-free LDS.128 gathers per position per word,
// running max, bias+ReLU at the end.
// ---------------------------------------------------------------------------
__device__ __forceinline__ void add4(float4& a, float4 b) {
    a.x += b.x; a.y += b.y; a.z += b.z; a.w += b.w;
}
__device__ __forceinline__ void max4(float4& a, float4 b) {
    a.x = fmaxf(a.x, b.x); a.y = fmaxf(a.y, b.y);
    a.z = fmaxf(a.z, b.z); a.w = fmaxf(a.w, b.w);
}

__global__ __launch_bounds__(32 * WPB, 2) void encode_kernel(const int* __restrict__ words,
                                                             const float* __restrict__ bias,
                                                             float* __restrict__ out) {
    extern __shared__ float4 Ps[];  // [KS*NL][SW4] float4 rows
    const int c0 = blockIdx.y * SW;

    // Stage this channel-slice of the P table.
    for (int idx = threadIdx.x; idx < KS * NL * SW4; idx += 32 * WPB) {
        int r = idx / SW4;
        int c = idx % SW4;
        int k = r >> 7, v = r & 127;
        Ps[idx] = *(const float4*)&g_P[k][v][c0 + c * 4];
    }
    __syncthreads();

    const int lane = threadIdx.x & 31;
    const int lo   = lane & 15;      // chunk index / letter position
    const int hsel = lane & 16;      // 0 = word A, 16 = word B
    const int warp = blockIdx.x * WPB + (threadIdx.x >> 5);
    const int nwarp = G_X * WPB;

    float4 bb = make_float4(0.f, 0.f, 0.f, 0.f);
    if (lo < SW4) bb = *(const float4*)&bias[c0 + lo * 4];

    for (int p = warp; p < NW / 2; p += nwarp) {
        const int gw = 2 * p + (hsel >> 4);  // this half-warp's word

        // Letters: lane reads letter `lo` of its half's word, then each lane
        // broadcasts from its own half via shfl.
        int cval = words[lo * NW + gw];
        int let[WL];
#pragma unroll
        for (int l = 0; l < WL; ++l)
            let[l] = __shfl_sync(0xffffffffu, cval, l | hsel);

        if (lo < SW4) {
            const float NEG = -1e30f;
            float4 a = make_float4(NEG, NEG, NEG, NEG);
#pragma unroll
            for (int l = 0; l < WL; ++l) {
                float4 sd = Ps[(NL + let[l]) * SW4 + lo];               // k=1
                if (l > 0)      add4(sd, Ps[let[l - 1] * SW4 + lo]);    // k=0
                if (l < WL - 1) add4(sd, Ps[(2 * NL + let[l + 1]) * SW4 + lo]);  // k=2
                max4(a, sd);
            }
            float4 r;
            r.x = fmaxf(a.x + bb.x, 0.f);
            r.y = fmaxf(a.y + bb.y, 0.f);
            r.z = fmaxf(a.z + bb.z, 0.f);
            r.w = fmaxf(a.w + bb.w, 0.f);
            *(float4*)&out[(size_t)gw * D + c0 + lo * 4] = r;
        }
    }
}

// ---------------------------------------------------------------------------
// Launch. Inputs: words(int32), emb(f32), conv_w(f32), conv_b(f32). Out f32.
// ---------------------------------------------------------------------------
extern "C" void kernel_launch(void* const* d_in, const int* in_sizes, int n_in,
                              void* d_out, int out_size) {
    const int*   words = (const int*)d_in[0];
    const float* emb   = (const float*)d_in[1];
    const float* w     = (const float*)d_in[2];
    const float* b     = (const float*)d_in[3];
    float*       out   = (float*)d_out;

    compute_P_kernel<<<D, 128>>>(emb, w);

    cudaFuncSetAttribute(encode_kernel,
                         cudaFuncAttributeMaxDynamicSharedMemorySize, ENC_SMEM);
    encode_kernel<<<dim3(G_X, NSL), 32 * WPB, ENC_SMEM>>>(words, b, out);
}

// round 4
// speedup vs baseline: 1.9048x; 1.0810x over previous
#include <cuda_runtime.h>
#include <cuda_fp16.h>

// Problem constants
#define NW 16384   // words
#define WL 16      // word length
#define D  300     // hidden dim
#define DP 320     // padded channel count for fp16 table (16B-aligned rows)
#define NL 128     // letters
#define KS 3       // conv taps

// Encode config: slices of 128 ch (c0 = 0,128,256; slice 2 has 44 real ch)
#define WPB 16
#define ENC_THREADS 512
#define B0 119
#define B1 119
#define B2 59
#define ENC_BLOCKS (B0 + B1 + B2)           // 297
#define ENC_SMEM (KS * NL * 128 * 2)        // 98304 B (96 KB) -> 2 CTA/SM

// Per-letter conv partials in fp16: g_Ph[k][v][o], o padded to DP (pad = 0)
__device__ __half g_Ph[KS][NL][DP];

// ---------------------------------------------------------------------------
// Kernel 1: build P. 160 blocks x 256 threads = (2 output ch) x (128 letters).
// w rows staged in smem (broadcast reads); emb rows read as float4 (L1 reuse
// across the 2 o-threads sharing a letter). Writes fp16 incl. zeroed pad.
// ---------------------------------------------------------------------------
__global__ __launch_bounds__(256) void compute_P_kernel(const float* __restrict__ emb,
                                                        const float* __restrict__ w) {
    __shared__ float ws[2][D * KS];  // two w rows, 7.2 KB
    const int ob = blockIdx.x * 2;   // output channel base (0..318)
    for (int idx = threadIdx.x; idx < 2 * D * KS; idx += 256) {
        int ol = idx / (D * KS), r = idx % (D * KS);
        int o = ob + ol;
        ws[ol][r] = (o < D) ? w[o * D * KS + r] : 0.f;
    }
    __syncthreads();

    const int v  = threadIdx.x & 127;
    const int ol = threadIdx.x >> 7;
    const int o  = ob + ol;
    const float4* er = (const float4*)(emb + v * D);
    const float* wr = ws[ol];
    float a0 = 0.f, a1 = 0.f, a2 = 0.f;
#pragma unroll
    for (int c = 0; c < D / 4; ++c) {
        float4 e = __ldg(er + c);
        a0 = fmaf(e.x, wr[c*12+0],  a0); a1 = fmaf(e.x, wr[c*12+1],  a1); a2 = fmaf(e.x, wr[c*12+2],  a2);
        a0 = fmaf(e.y, wr[c*12+3],  a0); a1 = fmaf(e.y, wr[c*12+4],  a1); a2 = fmaf(e.y, wr[c*12+5],  a2);
        a0 = fmaf(e.z, wr[c*12+6],  a0); a1 = fmaf(e.z, wr[c*12+7],  a1); a2 = fmaf(e.z, wr[c*12+8],  a2);
        a0 = fmaf(e.w, wr[c*12+9],  a0); a1 = fmaf(e.w, wr[c*12+10], a1); a2 = fmaf(e.w, wr[c*12+11], a2);
    }
    g_Ph[0][v][o] = __float2half(a0);
    g_Ph[1][v][o] = __float2half(a1);
    g_Ph[2][v][o] = __float2half(a2);
}

// ---------------------------------------------------------------------------
// Kernel 2: encode. 297 blocks, 512 thr. Block stages its 128-ch fp16 P-slice
// (96 KB) in smem; each warp processes 2 words (half-warp each). Per position:
// 3 conflict-free LDS.128 + half2 adds + half2 running max. Bias + ReLU in
// fp32 at the end.
// ---------------------------------------------------------------------------
__global__ __launch_bounds__(ENC_THREADS, 2) void encode_kernel(const int* __restrict__ words,
                                                                const float* __restrict__ bias,
                                                                float* __restrict__ out) {
    extern __shared__ uint4 Pv[];  // [KS*NL rows][16 uint4] (8 halves per uint4)

    // slice decode: blocks [0,119) -> s0, [119,238) -> s1, [238,297) -> s2
    int b = blockIdx.x;
    int slice, lb, nb;
    if (b < B0)            { slice = 0; lb = b;            nb = B0; }
    else if (b < B0 + B1)  { slice = 1; lb = b - B0;       nb = B1; }
    else                   { slice = 2; lb = b - B0 - B1;  nb = B2; }
    const int c0 = slice * 128;
    const int nchunk = (slice == 2) ? 8 : 16;  // valid uint4 chunks per row

    // Stage the slice: row r = k*128+v -> smem row stride 16 uint4 (256 B).
    const uint4* gP = (const uint4*)g_Ph;  // row stride DP/8 = 40 uint4
    for (int idx = threadIdx.x; idx < KS * NL * nchunk; idx += ENC_THREADS) {
        int r = idx / nchunk, c = idx % nchunk;
        Pv[r * 16 + c] = gP[r * (DP / 8) + slice * 16 + c];
    }
    __syncthreads();

    const int lane  = threadIdx.x & 31;
    const int lo    = lane & 15;
    const int hsel  = lane & 16;
    const int wid   = threadIdx.x >> 5;
    const int wsl   = lb * WPB + wid;   // warp index within slice
    const int nwarp = nb * WPB;

    const bool active = lo < nchunk;
    const int ch = c0 + lo * 8;

    float4 bb0 = make_float4(0.f, 0.f, 0.f, 0.f);
    float4 bb1 = bb0;
    if (active) {
        if (ch < D)     bb0 = *(const float4*)&bias[ch];
        if (ch + 4 < D) bb1 = *(const float4*)&bias[ch + 4];
    }

    const __half NH = __ushort_as_half((unsigned short)0xFC00);  // -inf
    const half2 NEGI = __halves2half2(NH, NH);

    for (int p = wsl; p < NW / 2; p += nwarp) {
        const int gw = 2 * p + (hsel >> 4);

        // letters of this half-warp's word (words is [WL, NW], WL == 16)
        int cval = words[lo * NW + gw];
        int idx[WL];
#pragma unroll
        for (int l = 0; l < WL; ++l)
            idx[l] = __shfl_sync(0xffffffffu, cval, l | hsel) * 16 + lo;

        if (active) {
            half2 m0 = NEGI, m1 = NEGI, m2 = NEGI, m3 = NEGI;
#pragma unroll
            for (int l = 0; l < WL; ++l) {
                uint4 a = Pv[NL * 16 + idx[l]];  // k=1, this char
                half2 h0 = *(half2*)&a.x, h1 = *(half2*)&a.y;
                half2 h2 = *(half2*)&a.z, h3 = *(half2*)&a.w;
                if (l > 0) {
                    uint4 q = Pv[idx[l - 1]];    // k=0, prev char
                    h0 = __hadd2(h0, *(half2*)&q.x); h1 = __hadd2(h1, *(half2*)&q.y);
                    h2 = __hadd2(h2, *(half2*)&q.z); h3 = __hadd2(h3, *(half2*)&q.w);
                }
                if (l < WL - 1) {
                    uint4 q = Pv[2 * NL * 16 + idx[l + 1]];  // k=2, next char
                    h0 = __hadd2(h0, *(half2*)&q.x); h1 = __hadd2(h1, *(half2*)&q.y);
                    h2 = __hadd2(h2, *(half2*)&q.z); h3 = __hadd2(h3, *(half2*)&q.w);
                }
                m0 = __hmax2(m0, h0); m1 = __hmax2(m1, h1);
                m2 = __hmax2(m2, h2); m3 = __hmax2(m3, h3);
            }

            float2 f0 = __half22float2(m0), f1 = __half22float2(m1);
            float2 f2 = __half22float2(m2), f3 = __half22float2(m3);
            float* op = out + (size_t)gw * D + ch;
            if (ch < D) {
                float4 r;
                r.x = fmaxf(f0.x + bb0.x, 0.f); r.y = fmaxf(f0.y + bb0.y, 0.f);
                r.z = fmaxf(f1.x + bb0.z, 0.f); r.w = fmaxf(f1.y + bb0.w, 0.f);
                *(float4*)op = r;
            }
            if (ch + 4 < D) {
                float4 r;
                r.x = fmaxf(f2.x + bb1.x, 0.f); r.y = fmaxf(f2.y + bb1.y, 0.f);
                r.z = fmaxf(f3.x + bb1.z, 0.f); r.w = fmaxf(f3.y + bb1.w, 0.f);
                *(float4*)(op + 4) = r;
            }
        }
    }
}

// ---------------------------------------------------------------------------
// Launch. Inputs: words(int32), emb(f32), conv_w(f32), conv_b(f32). Out f32.
// ---------------------------------------------------------------------------
extern "C" void kernel_launch(void* const* d_in, const int* in_sizes, int n_in,
                              void* d_out, int out_size) {
    const int*   words = (const int*)d_in[0];
    const float* emb   = (const float*)d_in[1];
    const float* w     = (const float*)d_in[2];
    const float* b     = (const float*)d_in[3];
    float*       out   = (float*)d_out;

    compute_P_kernel<<<DP / 2, 256>>>(emb, w);

    cudaFuncSetAttribute(encode_kernel,
                         cudaFuncAttributeMaxDynamicSharedMemorySize, ENC_SMEM);
    encode_kernel<<<ENC_BLOCKS, ENC_THREADS, ENC_SMEM>>>(words, b, out);
}